// round 1
// baseline (speedup 1.0000x reference)
#include <cuda_runtime.h>
#include <math.h>

#define NMAX 50000
#define FIN 16
#define TT 12
#define HID 32
#define FT (FIN*TT)   // 192 floats per node

// ---------------- scratch (static device globals; no allocation) ----------------
__device__ float g_deg[NMAX];                 // degree, then rsqrt(degree)
__device__ float g_agg[(size_t)NMAX * FT];    // aggregated features [N,16,12] (same flat layout as x)
__device__ float g_A[3 * FIN * HID];          // folded W_g @ L_g_top
__device__ float g_c[3 * HID];                // folded biases
__device__ float g_probs[TT];                 // softmax(att)
__device__ float g_hsum[HID];                 // sum over nodes of relu(Hacc)

// ---------------- helpers ----------------
__device__ __forceinline__ void red4(float* p, float a, float b, float c, float d) {
    asm volatile("red.global.add.v4.f32 [%0], {%1,%2,%3,%4};"
                 :: "l"(p), "f"(a), "f"(b), "f"(c), "f"(d) : "memory");
}

__device__ __forceinline__ float sigf(float x) {
    return __fdividef(1.0f, 1.0f + __expf(-x));
}
__device__ __forceinline__ float tanhfast(float x) {
    // tanh(x) = 2*sigmoid(2x) - 1 ; __expf handles +-inf saturation correctly
    return fmaf(2.0f, __fdividef(1.0f, 1.0f + __expf(-2.0f * x)), -1.0f);
}

// ---------------- kernels ----------------
__global__ void k_init(int N) {
    int i = blockIdx.x * blockDim.x + threadIdx.x;
    if (i < N) g_deg[i] = 1.0f;            // self-loop contributes 1 to degree
    if (i < HID) g_hsum[i] = 0.0f;
}

__global__ void k_deg(const int* __restrict__ ei, int E) {
    int e = blockIdx.x * blockDim.x + threadIdx.x;
    if (e < E) atomicAdd(&g_deg[ei[E + e]], 1.0f);
}

__global__ void k_dis(int N) {
    int i = blockIdx.x * blockDim.x + threadIdx.x;
    if (i < N) g_deg[i] = rsqrtf(g_deg[i]);   // deg >= 1 always
}

// Precompute folded matrices A_g = W_g @ L_g[0:32,:], c_g = b_g @ L_g[0:32,:] + Lgb,
// and softmax(att). One block of 512 threads.
__global__ void k_prep(const float* __restrict__ Wz, const float* __restrict__ bz,
                       const float* __restrict__ Wr, const float* __restrict__ br,
                       const float* __restrict__ Wh, const float* __restrict__ bh,
                       const float* __restrict__ LzW, const float* __restrict__ Lzb,
                       const float* __restrict__ LrW, const float* __restrict__ Lrb,
                       const float* __restrict__ LhW, const float* __restrict__ Lhb,
                       const float* __restrict__ att) {
    int id = threadIdx.x;                       // 512 threads
    const float* W[3]  = {Wz, Wr, Wh};
    const float* L[3]  = {LzW, LrW, LhW};
    const float* bb[3] = {bz, br, bh};
    const float* Lb[3] = {Lzb, Lrb, Lhb};

    int f = id >> 5, j = id & 31;               // 16 x 32 = 512
    #pragma unroll
    for (int g = 0; g < 3; g++) {
        float s = 0.0f;
        #pragma unroll
        for (int k = 0; k < HID; k++)
            s = fmaf(W[g][f * HID + k], L[g][k * HID + j], s);
        g_A[(g * FIN + f) * HID + j] = s;
    }
    if (id < 3 * HID) {
        int g = id >> 5, jj = id & 31;
        float s = Lb[g][jj];
        #pragma unroll
        for (int k = 0; k < HID; k++)
            s = fmaf(bb[g][k], L[g][k * HID + jj], s);
        g_c[g * HID + jj] = s;
    }
    if (id == 0) {
        float m = att[0];
        for (int t = 1; t < TT; t++) m = fmaxf(m, att[t]);
        float sum = 0.0f;
        float ev[TT];
        for (int t = 0; t < TT; t++) { ev[t] = __expf(att[t] - m); sum += ev[t]; }
        float inv = __fdividef(1.0f, sum);
        for (int t = 0; t < TT; t++) g_probs[t] = ev[t] * inv;
    }
}

// Initialize agg with the self-loop term: agg[n,:] = (1/deg[n]) * x[n,:]
__global__ void k_agginit(const float* __restrict__ x, int N) {
    int i = blockIdx.x * blockDim.x + threadIdx.x;
    if (i >= N * (FT / 4)) return;
    int n = i / (FT / 4);
    float d = g_deg[n];                          // this is rsqrt(deg)
    float w = d * d;                             // 1/deg
    float4 v = __ldg(&((const float4*)x)[i]);
    ((float4*)g_agg)[i] = make_float4(w * v.x, w * v.y, w * v.z, w * v.w);
}

// Edge scatter: agg[dst] += norm * x[src], all 192 floats (48 float4 vector atomics)
__global__ void k_edge(const int* __restrict__ ei, const float* __restrict__ x, int E) {
    int e = blockIdx.x * blockDim.x + threadIdx.x;
    if (e >= E) return;
    int s = ei[e];
    int d = ei[E + e];
    float w = g_deg[s] * g_deg[d];               // dis[src]*dis[dst]
    const float4* xs = (const float4*)(x + (size_t)s * FT);
    float* ad = g_agg + (size_t)d * FT;
    #pragma unroll
    for (int q = 0; q < FT / 4; q++) {
        float4 v = __ldg(&xs[q]);
        red4(ad + q * 4, w * v.x, w * v.y, w * v.z, w * v.w);
    }
}

// Per-node GRU over T=12 steps, fully register-resident state; weights in shared.
__global__ void __launch_bounds__(128, 2)
k_gru(const float* __restrict__ LzW, const float* __restrict__ LrW,
      const float* __restrict__ LhW, int N) {
    __shared__ float4 sA[3][FIN][HID / 4];   // folded A matrices
    __shared__ float4 sB[3][HID][HID / 4];   // bottom halves of L matrices
    __shared__ float4 sc[3][HID / 4];        // folded biases
    __shared__ float  sp[TT];
    __shared__ float  bsum[HID];

    int tid = threadIdx.x;
    {
        float* pA = (float*)sA;
        for (int i = tid; i < 3 * FIN * HID; i += 128) pA[i] = g_A[i];
        float* pB = (float*)sB;
        for (int i = tid; i < HID * HID; i += 128) {
            pB[i]                 = LzW[HID * HID + i];
            pB[HID * HID + i]     = LrW[HID * HID + i];
            pB[2 * HID * HID + i] = LhW[HID * HID + i];
        }
        float* pc = (float*)sc;
        if (tid < 3 * HID) pc[tid] = g_c[tid];
        if (tid < TT) sp[tid] = g_probs[tid];
        if (tid < HID) bsum[tid] = 0.0f;
    }
    __syncthreads();

    int n = blockIdx.x * 128 + tid;
    if (n < N) {
        float H[HID], acc[HID];
        #pragma unroll
        for (int j = 0; j < HID; j++) { H[j] = 0.0f; acc[j] = 0.0f; }
        const float* ap = g_agg + (size_t)n * FT;

        #pragma unroll 1
        for (int t = 0; t < TT; t++) {
            float a[FIN];
            #pragma unroll
            for (int f = 0; f < FIN; f++) a[f] = __ldg(&ap[f * TT + t]);
            float p = sp[t];

            float Z[HID], R[HID];
            #pragma unroll
            for (int j4 = 0; j4 < HID / 4; j4++) {
                float4 z = sc[0][j4];
                float4 r = sc[1][j4];
                #pragma unroll
                for (int f = 0; f < FIN; f++) {
                    float av = a[f];
                    float4 wz = sA[0][f][j4];
                    float4 wr = sA[1][f][j4];
                    z.x = fmaf(av, wz.x, z.x); z.y = fmaf(av, wz.y, z.y);
                    z.z = fmaf(av, wz.z, z.z); z.w = fmaf(av, wz.w, z.w);
                    r.x = fmaf(av, wr.x, r.x); r.y = fmaf(av, wr.y, r.y);
                    r.z = fmaf(av, wr.z, r.z); r.w = fmaf(av, wr.w, r.w);
                }
                #pragma unroll
                for (int k = 0; k < HID; k++) {
                    float hk = H[k];
                    float4 bz4 = sB[0][k][j4];
                    float4 br4 = sB[1][k][j4];
                    z.x = fmaf(hk, bz4.x, z.x); z.y = fmaf(hk, bz4.y, z.y);
                    z.z = fmaf(hk, bz4.z, z.z); z.w = fmaf(hk, bz4.w, z.w);
                    r.x = fmaf(hk, br4.x, r.x); r.y = fmaf(hk, br4.y, r.y);
                    r.z = fmaf(hk, br4.z, r.z); r.w = fmaf(hk, br4.w, r.w);
                }
                Z[4 * j4 + 0] = sigf(z.x); Z[4 * j4 + 1] = sigf(z.y);
                Z[4 * j4 + 2] = sigf(z.z); Z[4 * j4 + 3] = sigf(z.w);
                R[4 * j4 + 0] = sigf(r.x); R[4 * j4 + 1] = sigf(r.y);
                R[4 * j4 + 2] = sigf(r.z); R[4 * j4 + 3] = sigf(r.w);
            }
            // R <- H * R (reset-gated state)
            #pragma unroll
            for (int k = 0; k < HID; k++) R[k] *= H[k];

            #pragma unroll
            for (int j4 = 0; j4 < HID / 4; j4++) {
                float4 h = sc[2][j4];
                #pragma unroll
                for (int f = 0; f < FIN; f++) {
                    float av = a[f];
                    float4 wh = sA[2][f][j4];
                    h.x = fmaf(av, wh.x, h.x); h.y = fmaf(av, wh.y, h.y);
                    h.z = fmaf(av, wh.z, h.z); h.w = fmaf(av, wh.w, h.w);
                }
                #pragma unroll
                for (int k = 0; k < HID; k++) {
                    float rk = R[k];
                    float4 bh4 = sB[2][k][j4];
                    h.x = fmaf(rk, bh4.x, h.x); h.y = fmaf(rk, bh4.y, h.y);
                    h.z = fmaf(rk, bh4.z, h.z); h.w = fmaf(rk, bh4.w, h.w);
                }
                int j = 4 * j4;
                {
                    float ht = tanhfast(h.x); float zt = Z[j + 0];
                    H[j + 0] = zt * H[j + 0] + (1.0f - zt) * ht;
                    acc[j + 0] = fmaf(p, H[j + 0], acc[j + 0]);
                }
                {
                    float ht = tanhfast(h.y); float zt = Z[j + 1];
                    H[j + 1] = zt * H[j + 1] + (1.0f - zt) * ht;
                    acc[j + 1] = fmaf(p, H[j + 1], acc[j + 1]);
                }
                {
                    float ht = tanhfast(h.z); float zt = Z[j + 2];
                    H[j + 2] = zt * H[j + 2] + (1.0f - zt) * ht;
                    acc[j + 2] = fmaf(p, H[j + 2], acc[j + 2]);
                }
                {
                    float ht = tanhfast(h.w); float zt = Z[j + 3];
                    H[j + 3] = zt * H[j + 3] + (1.0f - zt) * ht;
                    acc[j + 3] = fmaf(p, H[j + 3], acc[j + 3]);
                }
            }
        }
        // per-node relu, then block-local reduction
        #pragma unroll
        for (int j = 0; j < HID; j++) {
            float v = acc[j] > 0.0f ? acc[j] : 0.0f;
            atomicAdd(&bsum[j], v);
        }
    }
    __syncthreads();
    if (tid < HID) atomicAdd(&g_hsum[tid], bsum[tid]);
}

__global__ void k_final(const float* __restrict__ linW, const float* __restrict__ linb,
                        float* out, int N) {
    int j = threadIdx.x;   // 32 threads
    float invN = 1.0f / (float)N;
    float v = g_hsum[j] * invN * linW[j];
    #pragma unroll
    for (int o = 16; o; o >>= 1) v += __shfl_xor_sync(0xffffffffu, v, o);
    if (j == 0) {
        float r = v + linb[0];
        out[0] = r > 0.0f ? r : 0.0f;
    }
}

// ---------------- launcher ----------------
extern "C" void kernel_launch(void* const* d_in, const int* in_sizes, int n_in,
                              void* d_out, int out_size) {
    const float* x    = (const float*)d_in[0];
    const int*   ei   = (const int*)  d_in[1];
    const float* att  = (const float*)d_in[2];
    const float* Wz   = (const float*)d_in[3];
    const float* bz   = (const float*)d_in[4];
    const float* Wr   = (const float*)d_in[5];
    const float* br   = (const float*)d_in[6];
    const float* Wh   = (const float*)d_in[7];
    const float* bh   = (const float*)d_in[8];
    const float* LzW  = (const float*)d_in[9];
    const float* Lzb  = (const float*)d_in[10];
    const float* LrW  = (const float*)d_in[11];
    const float* Lrb  = (const float*)d_in[12];
    const float* LhW  = (const float*)d_in[13];
    const float* Lhb  = (const float*)d_in[14];
    const float* linW = (const float*)d_in[15];
    const float* linb = (const float*)d_in[16];

    int N = in_sizes[0] / FT;
    int E = in_sizes[1] / 2;

    k_init<<<(N + 255) / 256, 256>>>(N);
    k_deg<<<(E + 255) / 256, 256>>>(ei, E);
    k_prep<<<1, 512>>>(Wz, bz, Wr, br, Wh, bh, LzW, Lzb, LrW, Lrb, LhW, Lhb, att);
    k_dis<<<(N + 255) / 256, 256>>>(N);
    k_agginit<<<(N * (FT / 4) + 255) / 256, 256>>>(x, N);
    k_edge<<<(E + 255) / 256, 256>>>(ei, x, E);
    k_gru<<<(N + 127) / 128, 128>>>(LzW, LrW, LhW, N);
    k_final<<<1, 32>>>(linW, linb, (float*)d_out, N);
}

// round 2
// speedup vs baseline: 1.5968x; 1.5968x over previous
#include <cuda_runtime.h>
#include <math.h>

#define NMAX 50000
#define EMAX 1600000
#define FIN 16
#define TT 12
#define HID 32
#define FT (FIN*TT)   // 192 floats per node

// ---------------- scratch (static device globals; no allocation) ----------------
__device__ int   g_cnt[NMAX];                    // in-degree counts (excl. self-loop)
__device__ int   g_rowptr[NMAX + 1];             // CSR row pointers
__device__ int   g_cur[NMAX];                    // fill cursors
__device__ int   g_srcs[EMAX];                   // CSR column (src node) array
__device__ float g_dis[NMAX];                    // rsqrt(degree incl. self-loop)
__device__ float g_agg[(size_t)NMAX * FT];       // aggregated features [N,16,12]
__device__ float g_A[3 * FIN * HID];             // folded W_g @ L_g_top
__device__ float g_c[3 * HID];                   // folded biases
__device__ float g_probs[TT];                    // softmax(att)
__device__ float g_hsum[HID];                    // sum over nodes of relu(Hacc)

// ---------------- helpers ----------------
__device__ __forceinline__ float sigf(float x) {
    return __fdividef(1.0f, 1.0f + __expf(-x));
}
__device__ __forceinline__ float tanhfast(float x) {
    return fmaf(2.0f, __fdividef(1.0f, 1.0f + __expf(-2.0f * x)), -1.0f);
}

// ---------------- kernels ----------------
__global__ void k_zero(int N) {
    int i = blockIdx.x * blockDim.x + threadIdx.x;
    if (i < N) g_cnt[i] = 0;
    if (i < HID) g_hsum[i] = 0.0f;
}

__global__ void k_cnt(const int* __restrict__ ei, int E) {
    int e = blockIdx.x * blockDim.x + threadIdx.x;
    if (e < E) atomicAdd(&g_cnt[ei[E + e]], 1);
}

// Precompute folded matrices A_g = W_g @ L_g[0:32,:], c_g = b_g @ L_g[0:32,:] + Lgb,
// and softmax(att). One block of 512 threads.
__global__ void k_prep(const float* __restrict__ Wz, const float* __restrict__ bz,
                       const float* __restrict__ Wr, const float* __restrict__ br,
                       const float* __restrict__ Wh, const float* __restrict__ bh,
                       const float* __restrict__ LzW, const float* __restrict__ Lzb,
                       const float* __restrict__ LrW, const float* __restrict__ Lrb,
                       const float* __restrict__ LhW, const float* __restrict__ Lhb,
                       const float* __restrict__ att) {
    int id = threadIdx.x;                       // 512 threads
    const float* W[3]  = {Wz, Wr, Wh};
    const float* L[3]  = {LzW, LrW, LhW};
    const float* bb[3] = {bz, br, bh};
    const float* Lb[3] = {Lzb, Lrb, Lhb};

    int f = id >> 5, j = id & 31;               // 16 x 32 = 512
    #pragma unroll
    for (int g = 0; g < 3; g++) {
        float s = 0.0f;
        #pragma unroll
        for (int k = 0; k < HID; k++)
            s = fmaf(W[g][f * HID + k], L[g][k * HID + j], s);
        g_A[(g * FIN + f) * HID + j] = s;
    }
    if (id < 3 * HID) {
        int g = id >> 5, jj = id & 31;
        float s = Lb[g][jj];
        #pragma unroll
        for (int k = 0; k < HID; k++)
            s = fmaf(bb[g][k], L[g][k * HID + jj], s);
        g_c[g * HID + jj] = s;
    }
    if (id == 0) {
        float m = att[0];
        for (int t = 1; t < TT; t++) m = fmaxf(m, att[t]);
        float sum = 0.0f;
        float ev[TT];
        for (int t = 0; t < TT; t++) { ev[t] = __expf(att[t] - m); sum += ev[t]; }
        float inv = __fdividef(1.0f, sum);
        for (int t = 0; t < TT; t++) g_probs[t] = ev[t] * inv;
    }
}

// Single-block exclusive scan over g_cnt -> g_rowptr / g_cur; also g_dis.
__global__ void k_scan(int N) {
    __shared__ int wsum[32];
    const int tid  = threadIdx.x;              // 1024 threads
    const int lane = tid & 31;
    const int wid  = tid >> 5;
    const int chunk = (N + 1023) / 1024;
    int b = tid * chunk;
    int e = min(b + chunk, N);

    int s = 0;
    for (int i = b; i < e; i++) s += g_cnt[i];

    // inclusive warp scan of per-thread sums
    int v = s;
    #pragma unroll
    for (int o = 1; o < 32; o <<= 1) {
        int t = __shfl_up_sync(0xffffffffu, v, o);
        if (lane >= o) v += t;
    }
    if (lane == 31) wsum[wid] = v;
    __syncthreads();
    if (wid == 0) {
        int w = wsum[lane];
        #pragma unroll
        for (int o = 1; o < 32; o <<= 1) {
            int t = __shfl_up_sync(0xffffffffu, w, o);
            if (lane >= o) w += t;
        }
        wsum[lane] = w;
    }
    __syncthreads();

    int excl = v - s + (wid > 0 ? wsum[wid - 1] : 0);

    int run = excl;
    for (int i = b; i < e; i++) {
        int c = g_cnt[i];
        g_rowptr[i] = run;
        g_cur[i]    = run;
        g_dis[i]    = rsqrtf((float)(c + 1));   // +1 self-loop
        run += c;
    }
    if (b < N && e == N) g_rowptr[N] = run;
}

// CSR fill: place src of each edge into its dst's segment.
__global__ void k_fill(const int* __restrict__ ei, int E) {
    int e = blockIdx.x * blockDim.x + threadIdx.x;
    if (e >= E) return;
    int d = ei[E + e];
    int p = atomicAdd(&g_cur[d], 1);
    g_srcs[p] = ei[e];
}

// Warp-per-node gather: agg[n] = (1/deg)*x[n] + sum_edges dis[s]*dis[n]*x[s]
__global__ void __launch_bounds__(256)
k_gather(const float* __restrict__ x, int N) {
    int gw   = (blockIdx.x * blockDim.x + threadIdx.x) >> 5;
    int lane = threadIdx.x & 31;
    if (gw >= N) return;
    int n = gw;

    int beg = g_rowptr[n];
    int end = g_rowptr[n + 1];
    float dd = g_dis[n];

    float acc[6];
    {
        float inv = dd * dd;                       // 1/deg
        const float* xp = x + (size_t)n * FT;
        #pragma unroll
        for (int k = 0; k < 6; k++) acc[k] = inv * __ldg(&xp[lane + 32 * k]);
    }

    for (int i = beg; i < end; i += 32) {
        int j = i + lane;
        int   s = 0;
        float w = 0.0f;
        if (j < end) {
            s = g_srcs[j];
            w = g_dis[s] * dd;
        }
        int m = min(32, end - i);
        for (int u = 0; u < m; u++) {
            int   ss = __shfl_sync(0xffffffffu, s, u);
            float ww = __shfl_sync(0xffffffffu, w, u);
            const float* xp = x + (size_t)ss * FT;
            #pragma unroll
            for (int k = 0; k < 6; k++)
                acc[k] = fmaf(ww, __ldg(&xp[lane + 32 * k]), acc[k]);
        }
    }

    float* ap = g_agg + (size_t)n * FT;
    #pragma unroll
    for (int k = 0; k < 6; k++) ap[lane + 32 * k] = acc[k];
}

// Per-node GRU over T=12 steps, fully register-resident state; weights in shared.
__global__ void __launch_bounds__(128, 2)
k_gru(const float* __restrict__ LzW, const float* __restrict__ LrW,
      const float* __restrict__ LhW, int N) {
    __shared__ float4 sA[3][FIN][HID / 4];   // folded A matrices
    __shared__ float4 sB[3][HID][HID / 4];   // bottom halves of L matrices
    __shared__ float4 sc[3][HID / 4];        // folded biases
    __shared__ float  sp[TT];
    __shared__ float  bsum[HID];

    int tid = threadIdx.x;
    {
        float* pA = (float*)sA;
        for (int i = tid; i < 3 * FIN * HID; i += 128) pA[i] = g_A[i];
        float* pB = (float*)sB;
        for (int i = tid; i < HID * HID; i += 128) {
            pB[i]                 = LzW[HID * HID + i];
            pB[HID * HID + i]     = LrW[HID * HID + i];
            pB[2 * HID * HID + i] = LhW[HID * HID + i];
        }
        float* pc = (float*)sc;
        if (tid < 3 * HID) pc[tid] = g_c[tid];
        if (tid < TT) sp[tid] = g_probs[tid];
        if (tid < HID) bsum[tid] = 0.0f;
    }
    __syncthreads();

    int n = blockIdx.x * 128 + tid;
    if (n < N) {
        float H[HID], acc[HID];
        #pragma unroll
        for (int j = 0; j < HID; j++) { H[j] = 0.0f; acc[j] = 0.0f; }
        const float* ap = g_agg + (size_t)n * FT;

        #pragma unroll 1
        for (int t = 0; t < TT; t++) {
            float a[FIN];
            #pragma unroll
            for (int f = 0; f < FIN; f++) a[f] = __ldg(&ap[f * TT + t]);
            float p = sp[t];

            float Z[HID], R[HID];
            #pragma unroll
            for (int j4 = 0; j4 < HID / 4; j4++) {
                float4 z = sc[0][j4];
                float4 r = sc[1][j4];
                #pragma unroll
                for (int f = 0; f < FIN; f++) {
                    float av = a[f];
                    float4 wz = sA[0][f][j4];
                    float4 wr = sA[1][f][j4];
                    z.x = fmaf(av, wz.x, z.x); z.y = fmaf(av, wz.y, z.y);
                    z.z = fmaf(av, wz.z, z.z); z.w = fmaf(av, wz.w, z.w);
                    r.x = fmaf(av, wr.x, r.x); r.y = fmaf(av, wr.y, r.y);
                    r.z = fmaf(av, wr.z, r.z); r.w = fmaf(av, wr.w, r.w);
                }
                #pragma unroll
                for (int k = 0; k < HID; k++) {
                    float hk = H[k];
                    float4 bz4 = sB[0][k][j4];
                    float4 br4 = sB[1][k][j4];
                    z.x = fmaf(hk, bz4.x, z.x); z.y = fmaf(hk, bz4.y, z.y);
                    z.z = fmaf(hk, bz4.z, z.z); z.w = fmaf(hk, bz4.w, z.w);
                    r.x = fmaf(hk, br4.x, r.x); r.y = fmaf(hk, br4.y, r.y);
                    r.z = fmaf(hk, br4.z, r.z); r.w = fmaf(hk, br4.w, r.w);
                }
                Z[4 * j4 + 0] = sigf(z.x); Z[4 * j4 + 1] = sigf(z.y);
                Z[4 * j4 + 2] = sigf(z.z); Z[4 * j4 + 3] = sigf(z.w);
                R[4 * j4 + 0] = sigf(r.x); R[4 * j4 + 1] = sigf(r.y);
                R[4 * j4 + 2] = sigf(r.z); R[4 * j4 + 3] = sigf(r.w);
            }
            #pragma unroll
            for (int k = 0; k < HID; k++) R[k] *= H[k];

            #pragma unroll
            for (int j4 = 0; j4 < HID / 4; j4++) {
                float4 h = sc[2][j4];
                #pragma unroll
                for (int f = 0; f < FIN; f++) {
                    float av = a[f];
                    float4 wh = sA[2][f][j4];
                    h.x = fmaf(av, wh.x, h.x); h.y = fmaf(av, wh.y, h.y);
                    h.z = fmaf(av, wh.z, h.z); h.w = fmaf(av, wh.w, h.w);
                }
                #pragma unroll
                for (int k = 0; k < HID; k++) {
                    float rk = R[k];
                    float4 bh4 = sB[2][k][j4];
                    h.x = fmaf(rk, bh4.x, h.x); h.y = fmaf(rk, bh4.y, h.y);
                    h.z = fmaf(rk, bh4.z, h.z); h.w = fmaf(rk, bh4.w, h.w);
                }
                int j = 4 * j4;
                {
                    float ht = tanhfast(h.x); float zt = Z[j + 0];
                    H[j + 0] = zt * H[j + 0] + (1.0f - zt) * ht;
                    acc[j + 0] = fmaf(p, H[j + 0], acc[j + 0]);
                }
                {
                    float ht = tanhfast(h.y); float zt = Z[j + 1];
                    H[j + 1] = zt * H[j + 1] + (1.0f - zt) * ht;
                    acc[j + 1] = fmaf(p, H[j + 1], acc[j + 1]);
                }
                {
                    float ht = tanhfast(h.z); float zt = Z[j + 2];
                    H[j + 2] = zt * H[j + 2] + (1.0f - zt) * ht;
                    acc[j + 2] = fmaf(p, H[j + 2], acc[j + 2]);
                }
                {
                    float ht = tanhfast(h.w); float zt = Z[j + 3];
                    H[j + 3] = zt * H[j + 3] + (1.0f - zt) * ht;
                    acc[j + 3] = fmaf(p, H[j + 3], acc[j + 3]);
                }
            }
        }
        #pragma unroll
        for (int j = 0; j < HID; j++) {
            float v = acc[j] > 0.0f ? acc[j] : 0.0f;
            atomicAdd(&bsum[j], v);
        }
    }
    __syncthreads();
    if (tid < HID) atomicAdd(&g_hsum[tid], bsum[tid]);
}

__global__ void k_final(const float* __restrict__ linW, const float* __restrict__ linb,
                        float* out, int N) {
    int j = threadIdx.x;   // 32 threads
    float invN = 1.0f / (float)N;
    float v = g_hsum[j] * invN * linW[j];
    #pragma unroll
    for (int o = 16; o; o >>= 1) v += __shfl_xor_sync(0xffffffffu, v, o);
    if (j == 0) {
        float r = v + linb[0];
        out[0] = r > 0.0f ? r : 0.0f;
    }
}

// ---------------- launcher ----------------
extern "C" void kernel_launch(void* const* d_in, const int* in_sizes, int n_in,
                              void* d_out, int out_size) {
    const float* x    = (const float*)d_in[0];
    const int*   ei   = (const int*)  d_in[1];
    const float* att  = (const float*)d_in[2];
    const float* Wz   = (const float*)d_in[3];
    const float* bz   = (const float*)d_in[4];
    const float* Wr   = (const float*)d_in[5];
    const float* br   = (const float*)d_in[6];
    const float* Wh   = (const float*)d_in[7];
    const float* bh   = (const float*)d_in[8];
    const float* LzW  = (const float*)d_in[9];
    const float* Lzb  = (const float*)d_in[10];
    const float* LrW  = (const float*)d_in[11];
    const float* Lrb  = (const float*)d_in[12];
    const float* LhW  = (const float*)d_in[13];
    const float* Lhb  = (const float*)d_in[14];
    const float* linW = (const float*)d_in[15];
    const float* linb = (const float*)d_in[16];

    int N = in_sizes[0] / FT;
    int E = in_sizes[1] / 2;

    k_zero<<<(N + 255) / 256, 256>>>(N);
    k_cnt<<<(E + 255) / 256, 256>>>(ei, E);
    k_prep<<<1, 512>>>(Wz, bz, Wr, br, Wh, bh, LzW, Lzb, LrW, Lrb, LhW, Lhb, att);
    k_scan<<<1, 1024>>>(N);
    k_fill<<<(E + 255) / 256, 256>>>(ei, E);
    k_gather<<<(N * 32 + 255) / 256, 256>>>(x, N);
    k_gru<<<(N + 127) / 128, 128>>>(LzW, LrW, LhW, N);
    k_final<<<1, 32>>>(linW, linb, (float*)d_out, N);
}

// round 3
// speedup vs baseline: 1.8542x; 1.1612x over previous
#include <cuda_runtime.h>
#include <math.h>

#define NMAX 50000
#define EMAX 1600000
#define FIN 16
#define TT 12
#define HID 32
#define FT (FIN*TT)   // 192 floats per node
#define SB 512        // scan block size

// ---------------- scratch (static device globals; no allocation) ----------------
__device__ int   g_cnt[NMAX];                    // in-degree counts (excl. self-loop)
__device__ int   g_rowptr[NMAX + 1];             // CSR row pointers
__device__ int   g_cur[NMAX];                    // fill cursors
__device__ int2  g_sw[EMAX];                     // CSR payload: {src, bits(norm weight)}
__device__ int   g_part[256];                    // scan partials
__device__ float g_dis[NMAX];                    // rsqrt(degree incl. self-loop)
__device__ float g_agg[(size_t)NMAX * FT];       // aggregated features [N,16,12]
__device__ float g_A[3 * FIN * HID];             // folded W_g @ L_g_top
__device__ float g_c[3 * HID];                   // folded biases
__device__ float g_probs[TT];                    // softmax(att)
__device__ float g_hsum[HID];                    // sum over nodes of relu(Hacc)

// ---------------- helpers ----------------
__device__ __forceinline__ float sigf(float x) {
    return __fdividef(1.0f, 1.0f + __expf(-x));
}
__device__ __forceinline__ float tanhfast(float x) {
    return fmaf(2.0f, __fdividef(1.0f, 1.0f + __expf(-2.0f * x)), -1.0f);
}

// packed f32x2 helpers (Blackwell FFMA2)
typedef unsigned long long u64;
__device__ __forceinline__ u64 pk2(float x, float y) {
    u64 r; asm("mov.b64 %0, {%1,%2};" : "=l"(r) : "f"(x), "f"(y)); return r;
}
__device__ __forceinline__ u64 fma2(u64 a, u64 b, u64 c) {
    u64 d; asm("fma.rn.f32x2 %0, %1, %2, %3;" : "=l"(d) : "l"(a), "l"(b), "l"(c)); return d;
}
__device__ __forceinline__ void up2(u64 v, float& x, float& y) {
    asm("mov.b64 {%0,%1}, %2;" : "=f"(x), "=f"(y) : "l"(v));
}
union F4U2 { float4 f4; u64 u[2]; };

// ---------------- kernels ----------------
__global__ void k_zero(int N) {
    int i = blockIdx.x * blockDim.x + threadIdx.x;
    if (i < N) g_cnt[i] = 0;
    if (i < HID) g_hsum[i] = 0.0f;
}

__global__ void k_cnt(const int* __restrict__ ei, int E) {
    int e = blockIdx.x * blockDim.x + threadIdx.x;
    if (e < E) atomicAdd(&g_cnt[ei[E + e]], 1);
}

// Precompute folded matrices A_g = W_g @ L_g[0:32,:], c_g = b_g @ L_g[0:32,:] + Lgb,
// and softmax(att). One block of 512 threads.
__global__ void k_prep(const float* __restrict__ Wz, const float* __restrict__ bz,
                       const float* __restrict__ Wr, const float* __restrict__ br,
                       const float* __restrict__ Wh, const float* __restrict__ bh,
                       const float* __restrict__ LzW, const float* __restrict__ Lzb,
                       const float* __restrict__ LrW, const float* __restrict__ Lrb,
                       const float* __restrict__ LhW, const float* __restrict__ Lhb,
                       const float* __restrict__ att) {
    int id = threadIdx.x;                       // 512 threads
    const float* W[3]  = {Wz, Wr, Wh};
    const float* L[3]  = {LzW, LrW, LhW};
    const float* bb[3] = {bz, br, bh};
    const float* Lb[3] = {Lzb, Lrb, Lhb};

    int f = id >> 5, j = id & 31;               // 16 x 32 = 512
    #pragma unroll
    for (int g = 0; g < 3; g++) {
        float s = 0.0f;
        #pragma unroll
        for (int k = 0; k < HID; k++)
            s = fmaf(W[g][f * HID + k], L[g][k * HID + j], s);
        g_A[(g * FIN + f) * HID + j] = s;
    }
    if (id < 3 * HID) {
        int g = id >> 5, jj = id & 31;
        float s = Lb[g][jj];
        #pragma unroll
        for (int k = 0; k < HID; k++)
            s = fmaf(bb[g][k], L[g][k * HID + jj], s);
        g_c[g * HID + jj] = s;
    }
    if (id == 0) {
        float m = att[0];
        for (int t = 1; t < TT; t++) m = fmaxf(m, att[t]);
        float sum = 0.0f;
        float ev[TT];
        for (int t = 0; t < TT; t++) { ev[t] = __expf(att[t] - m); sum += ev[t]; }
        float inv = __fdividef(1.0f, sum);
        for (int t = 0; t < TT; t++) g_probs[t] = ev[t] * inv;
    }
}

// ---- parallel 3-phase scan ----
// phase A: per-block reduction of counts
__global__ void k_scan_a(int N) {
    __shared__ int ws[SB / 32];
    int tid = threadIdx.x;
    int i = blockIdx.x * SB + tid;
    int v = (i < N) ? g_cnt[i] : 0;
    #pragma unroll
    for (int o = 16; o; o >>= 1) v += __shfl_xor_sync(0xffffffffu, v, o);
    if ((tid & 31) == 0) ws[tid >> 5] = v;
    __syncthreads();
    if (tid < SB / 32) {
        int w = ws[tid];
        #pragma unroll
        for (int o = 8; o; o >>= 1) w += __shfl_xor_sync(0xffffu, w, o);
        if (tid == 0) g_part[blockIdx.x] = w;
    }
}

// phase B: exclusive scan of up to 128 block partials (1 block, 128 threads)
__global__ void k_scan_b(int NB, int N, int E) {
    __shared__ int ws[4];
    int tid = threadIdx.x, lane = tid & 31, wid = tid >> 5;
    int orig = (tid < NB) ? g_part[tid] : 0;
    int v = orig;
    #pragma unroll
    for (int o = 1; o < 32; o <<= 1) {
        int t = __shfl_up_sync(0xffffffffu, v, o);
        if (lane >= o) v += t;
    }
    if (lane == 31) ws[wid] = v;
    __syncthreads();
    if (wid == 0 && lane < 4) {
        int w = ws[lane];
        #pragma unroll
        for (int o = 1; o < 4; o <<= 1) {
            int t = __shfl_up_sync(0xfu, w, o);
            if (lane >= o) w += t;
        }
        ws[lane] = w;
    }
    __syncthreads();
    int incl = v + (wid > 0 ? ws[wid - 1] : 0);
    if (tid < NB) g_part[tid] = incl - orig;     // exclusive
    if (tid == 0) g_rowptr[N] = E;
}

// phase C: block-local exclusive scan + base offset; also rowptr/cur/dis
__global__ void k_scan_c(int N) {
    __shared__ int ws[SB / 32];
    int tid = threadIdx.x, lane = tid & 31, wid = tid >> 5;
    int i = blockIdx.x * SB + tid;
    int c = (i < N) ? g_cnt[i] : 0;
    int v = c;
    #pragma unroll
    for (int o = 1; o < 32; o <<= 1) {
        int t = __shfl_up_sync(0xffffffffu, v, o);
        if (lane >= o) v += t;
    }
    if (lane == 31) ws[wid] = v;
    __syncthreads();
    if (wid == 0 && lane < SB / 32) {
        int w = ws[lane];
        #pragma unroll
        for (int o = 1; o < SB / 32; o <<= 1) {
            int t = __shfl_up_sync((1u << (SB / 32)) - 1u, w, o);
            if (lane >= o) w += t;
        }
        ws[lane] = w;
    }
    __syncthreads();
    int excl = v - c + (wid > 0 ? ws[wid - 1] : 0) + g_part[blockIdx.x];
    if (i < N) {
        g_rowptr[i] = excl;
        g_cur[i]    = excl;
        g_dis[i]    = rsqrtf((float)(c + 1));    // +1 self-loop
    }
}

// CSR fill with folded norm weight: payload {src, dis[s]*dis[d]}
__global__ void k_fill(const int* __restrict__ ei, int E) {
    int e = blockIdx.x * blockDim.x + threadIdx.x;
    if (e >= E) return;
    int s = ei[e];
    int d = ei[E + e];
    int p = atomicAdd(&g_cur[d], 1);
    g_sw[p] = make_int2(s, __float_as_int(g_dis[s] * g_dis[d]));
}

// Warp-per-node gather: agg[n] = (1/deg)*x[n] + sum_edges w*x[s]
__global__ void __launch_bounds__(256)
k_gather(const float* __restrict__ x, int N) {
    __shared__ int2 stage[8][32];
    int gw   = (blockIdx.x * blockDim.x + threadIdx.x) >> 5;
    int wloc = threadIdx.x >> 5;
    int lane = threadIdx.x & 31;
    if (gw >= N) return;
    int n = gw;

    int beg = g_rowptr[n];
    int end = g_rowptr[n + 1];
    float dd = g_dis[n];

    float acc[6];
    {
        float inv = dd * dd;                       // 1/deg (self-loop term)
        const float* xp = x + (size_t)n * FT;
        #pragma unroll
        for (int k = 0; k < 6; k++) acc[k] = inv * __ldg(&xp[lane + 32 * k]);
    }

    for (int i = beg; i < end; i += 32) {
        int j = i + lane;
        if (j < end) stage[wloc][lane] = g_sw[j];
        __syncwarp();
        int m = min(32, end - i);
        #pragma unroll 4
        for (int u = 0; u < m; u++) {
            int2 sw = stage[wloc][u];
            float ww = __int_as_float(sw.y);
            const float* xp = x + (size_t)sw.x * FT;
            #pragma unroll
            for (int k = 0; k < 6; k++)
                acc[k] = fmaf(ww, __ldg(&xp[lane + 32 * k]), acc[k]);
        }
        __syncwarp();
    }

    float* ap = g_agg + (size_t)n * FT;
    #pragma unroll
    for (int k = 0; k < 6; k++) ap[lane + 32 * k] = acc[k];
}

// Per-node GRU over T=12 steps, packed f32x2 math; weights in shared.
__global__ void __launch_bounds__(128, 2)
k_gru(const float* __restrict__ LzW, const float* __restrict__ LrW,
      const float* __restrict__ LhW, int N) {
    __shared__ float4 sA[3][FIN][HID / 4];   // folded A matrices
    __shared__ float4 sB[3][HID][HID / 4];   // bottom halves of L matrices
    __shared__ float4 sc[3][HID / 4];        // folded biases
    __shared__ float  sp[TT];
    __shared__ float  bsum[HID];

    int tid = threadIdx.x;
    {
        float* pA = (float*)sA;
        for (int i = tid; i < 3 * FIN * HID; i += 128) pA[i] = g_A[i];
        float* pB = (float*)sB;
        for (int i = tid; i < HID * HID; i += 128) {
            pB[i]                 = LzW[HID * HID + i];
            pB[HID * HID + i]     = LrW[HID * HID + i];
            pB[2 * HID * HID + i] = LhW[HID * HID + i];
        }
        float* pc = (float*)sc;
        if (tid < 3 * HID) pc[tid] = g_c[tid];
        if (tid < TT) sp[tid] = g_probs[tid];
        if (tid < HID) bsum[tid] = 0.0f;
    }
    __syncthreads();

    int n = blockIdx.x * 128 + tid;
    if (n < N) {
        float H[HID], acc[HID];
        #pragma unroll
        for (int j = 0; j < HID; j++) { H[j] = 0.0f; acc[j] = 0.0f; }
        const float* ap = g_agg + (size_t)n * FT;

        #pragma unroll 1
        for (int t = 0; t < TT; t++) {
            float a[FIN];
            #pragma unroll
            for (int f = 0; f < FIN; f++) a[f] = __ldg(&ap[f * TT + t]);
            float p = sp[t];

            // ---- z, r pre-activations (packed pairs) ----
            u64 z[HID / 2], r[HID / 2];
            #pragma unroll
            for (int j4 = 0; j4 < HID / 4; j4++) {
                F4U2 cz; cz.f4 = sc[0][j4];
                F4U2 cr; cr.f4 = sc[1][j4];
                z[2 * j4] = cz.u[0]; z[2 * j4 + 1] = cz.u[1];
                r[2 * j4] = cr.u[0]; r[2 * j4 + 1] = cr.u[1];
            }
            #pragma unroll 4
            for (int f = 0; f < FIN; f++) {
                u64 av = pk2(a[f], a[f]);
                #pragma unroll
                for (int j4 = 0; j4 < HID / 4; j4++) {
                    F4U2 wz; wz.f4 = sA[0][f][j4];
                    F4U2 wr; wr.f4 = sA[1][f][j4];
                    z[2 * j4]     = fma2(av, wz.u[0], z[2 * j4]);
                    z[2 * j4 + 1] = fma2(av, wz.u[1], z[2 * j4 + 1]);
                    r[2 * j4]     = fma2(av, wr.u[0], r[2 * j4]);
                    r[2 * j4 + 1] = fma2(av, wr.u[1], r[2 * j4 + 1]);
                }
            }
            #pragma unroll 4
            for (int k = 0; k < HID; k++) {
                u64 hk = pk2(H[k], H[k]);
                #pragma unroll
                for (int j4 = 0; j4 < HID / 4; j4++) {
                    F4U2 wz; wz.f4 = sB[0][k][j4];
                    F4U2 wr; wr.f4 = sB[1][k][j4];
                    z[2 * j4]     = fma2(hk, wz.u[0], z[2 * j4]);
                    z[2 * j4 + 1] = fma2(hk, wz.u[1], z[2 * j4 + 1]);
                    r[2 * j4]     = fma2(hk, wr.u[0], r[2 * j4]);
                    r[2 * j4 + 1] = fma2(hk, wr.u[1], r[2 * j4 + 1]);
                }
            }
            float Z[HID], R[HID];
            #pragma unroll
            for (int j2 = 0; j2 < HID / 2; j2++) {
                float x0, x1;
                up2(z[j2], x0, x1);
                Z[2 * j2] = sigf(x0); Z[2 * j2 + 1] = sigf(x1);
                up2(r[j2], x0, x1);
                R[2 * j2]     = sigf(x0) * H[2 * j2];
                R[2 * j2 + 1] = sigf(x1) * H[2 * j2 + 1];
            }

            // ---- candidate h (packed pairs) ----
            u64 h[HID / 2];
            #pragma unroll
            for (int j4 = 0; j4 < HID / 4; j4++) {
                F4U2 ch; ch.f4 = sc[2][j4];
                h[2 * j4] = ch.u[0]; h[2 * j4 + 1] = ch.u[1];
            }
            #pragma unroll 4
            for (int f = 0; f < FIN; f++) {
                u64 av = pk2(a[f], a[f]);
                #pragma unroll
                for (int j4 = 0; j4 < HID / 4; j4++) {
                    F4U2 wh; wh.f4 = sA[2][f][j4];
                    h[2 * j4]     = fma2(av, wh.u[0], h[2 * j4]);
                    h[2 * j4 + 1] = fma2(av, wh.u[1], h[2 * j4 + 1]);
                }
            }
            #pragma unroll 4
            for (int k = 0; k < HID; k++) {
                u64 rk = pk2(R[k], R[k]);
                #pragma unroll
                for (int j4 = 0; j4 < HID / 4; j4++) {
                    F4U2 wh; wh.f4 = sB[2][k][j4];
                    h[2 * j4]     = fma2(rk, wh.u[0], h[2 * j4]);
                    h[2 * j4 + 1] = fma2(rk, wh.u[1], h[2 * j4 + 1]);
                }
            }
            #pragma unroll
            for (int j2 = 0; j2 < HID / 2; j2++) {
                float h0, h1;
                up2(h[j2], h0, h1);
                int j = 2 * j2;
                {
                    float ht = tanhfast(h0); float zt = Z[j];
                    H[j] = zt * H[j] + (1.0f - zt) * ht;
                    acc[j] = fmaf(p, H[j], acc[j]);
                }
                {
                    float ht = tanhfast(h1); float zt = Z[j + 1];
                    H[j + 1] = zt * H[j + 1] + (1.0f - zt) * ht;
                    acc[j + 1] = fmaf(p, H[j + 1], acc[j + 1]);
                }
            }
        }
        #pragma unroll
        for (int j = 0; j < HID; j++) {
            float v = acc[j] > 0.0f ? acc[j] : 0.0f;
            atomicAdd(&bsum[j], v);
        }
    }
    __syncthreads();
    if (tid < HID) atomicAdd(&g_hsum[tid], bsum[tid]);
}

__global__ void k_final(const float* __restrict__ linW, const float* __restrict__ linb,
                        float* out, int N) {
    int j = threadIdx.x;   // 32 threads
    float invN = 1.0f / (float)N;
    float v = g_hsum[j] * invN * linW[j];
    #pragma unroll
    for (int o = 16; o; o >>= 1) v += __shfl_xor_sync(0xffffffffu, v, o);
    if (j == 0) {
        float r = v + linb[0];
        out[0] = r > 0.0f ? r : 0.0f;
    }
}

// ---------------- launcher ----------------
extern "C" void kernel_launch(void* const* d_in, const int* in_sizes, int n_in,
                              void* d_out, int out_size) {
    const float* x    = (const float*)d_in[0];
    const int*   ei   = (const int*)  d_in[1];
    const float* att  = (const float*)d_in[2];
    const float* Wz   = (const float*)d_in[3];
    const float* bz   = (const float*)d_in[4];
    const float* Wr   = (const float*)d_in[5];
    const float* br   = (const float*)d_in[6];
    const float* Wh   = (const float*)d_in[7];
    const float* bh   = (const float*)d_in[8];
    const float* LzW  = (const float*)d_in[9];
    const float* Lzb  = (const float*)d_in[10];
    const float* LrW  = (const float*)d_in[11];
    const float* Lrb  = (const float*)d_in[12];
    const float* LhW  = (const float*)d_in[13];
    const float* Lhb  = (const float*)d_in[14];
    const float* linW = (const float*)d_in[15];
    const float* linb = (const float*)d_in[16];

    int N = in_sizes[0] / FT;
    int E = in_sizes[1] / 2;
    int NB = (N + SB - 1) / SB;

    k_zero<<<(N + 255) / 256, 256>>>(N);
    k_cnt<<<(E + 255) / 256, 256>>>(ei, E);
    k_prep<<<1, 512>>>(Wz, bz, Wr, br, Wh, bh, LzW, Lzb, LrW, Lrb, LhW, Lhb, att);
    k_scan_a<<<NB, SB>>>(N);
    k_scan_b<<<1, 128>>>(NB, N, E);
    k_scan_c<<<NB, SB>>>(N);
    k_fill<<<(E + 255) / 256, 256>>>(ei, E);
    k_gather<<<(N * 32 + 255) / 256, 256>>>(x, N);
    k_gru<<<(N + 127) / 128, 128>>>(LzW, LrW, LhW, N);
    k_final<<<1, 32>>>(linW, linb, (float*)d_out, N);
}

// round 4
// speedup vs baseline: 2.1075x; 1.1366x over previous
#include <cuda_runtime.h>
#include <cuda_fp16.h>
#include <math.h>

#define NMAX 50000
#define EMAX 1600000
#define FIN 16
#define TT 12
#define HID 32
#define FT (FIN*TT)   // 192 values per node
#define SB 512        // scan block size

// ---------------- scratch (static device globals; no allocation) ----------------
__device__ int    g_cnt[NMAX];                    // in-degree counts (excl. self-loop)
__device__ int    g_rowptr[NMAX + 1];             // CSR row pointers
__device__ int    g_cur[NMAX];                    // fill cursors
__device__ int2   g_sw[EMAX];                     // CSR payload: {src, bits(norm weight)}
__device__ int    g_part[256];                    // scan partials
__device__ float  g_dis[NMAX];                    // rsqrt(degree incl. self-loop)
__device__ __half g_xh[(size_t)NMAX * FT];        // fp16 features, t-major [N][T][F]
__device__ float  g_agg[(size_t)NMAX * FT];       // aggregated features, t-major [N][T][F]
__device__ float  g_A[3 * FIN * HID];             // folded W_g @ L_g_top
__device__ float  g_c[3 * HID];                   // folded biases
__device__ float  g_probs[TT];                    // softmax(att)
__device__ float  g_hsum[HID];                    // sum over nodes of relu(Hacc)

// ---------------- helpers ----------------
__device__ __forceinline__ float sigf(float x) {
    return __fdividef(1.0f, 1.0f + __expf(-x));
}
__device__ __forceinline__ float tanhfast(float x) {
    return fmaf(2.0f, __fdividef(1.0f, 1.0f + __expf(-2.0f * x)), -1.0f);
}

// packed f32x2 helpers (Blackwell FFMA2)
typedef unsigned long long u64;
__device__ __forceinline__ u64 pk2(float x, float y) {
    u64 r; asm("mov.b64 %0, {%1,%2};" : "=l"(r) : "f"(x), "f"(y)); return r;
}
__device__ __forceinline__ u64 fma2(u64 a, u64 b, u64 c) {
    u64 d; asm("fma.rn.f32x2 %0, %1, %2, %3;" : "=l"(d) : "l"(a), "l"(b), "l"(c)); return d;
}
__device__ __forceinline__ void up2(u64 v, float& x, float& y) {
    asm("mov.b64 {%0,%1}, %2;" : "=f"(x), "=f"(y) : "l"(v));
}
union F4U2 { float4 f4; u64 u[2]; };
union F4H2 { float4 f4; __half2 h2[4]; };

// ---------------- kernels ----------------
__global__ void k_zero(int N) {
    int i = blockIdx.x * blockDim.x + threadIdx.x;
    if (i < N) g_cnt[i] = 0;
    if (i < HID) g_hsum[i] = 0.0f;
}

__global__ void k_cnt(const int* __restrict__ ei, int E) {
    int e = blockIdx.x * blockDim.x + threadIdx.x;
    if (e < E) atomicAdd(&g_cnt[ei[E + e]], 1);
}

// Convert x [N][F][T] fp32 -> g_xh [N][T][F] fp16. 4 nodes per block of 256.
__global__ void k_half(const float* __restrict__ x, int N) {
    __shared__ float sx[4 * FT];
    int tid = threadIdx.x;
    size_t base = (size_t)blockIdx.x * 4 * FT;
    size_t lim  = (size_t)N * FT;
    #pragma unroll
    for (int i = tid; i < 4 * FT; i += 256) {
        size_t g = base + i;
        if (g < lim) sx[i] = x[g];
    }
    __syncthreads();
    #pragma unroll
    for (int i = tid; i < 4 * FT; i += 256) {
        size_t g = base + i;
        if (g < lim) {
            int nn = i / FT, p = i % FT;
            int t = p / FIN, f = p % FIN;
            g_xh[g] = __float2half(sx[nn * FT + f * TT + t]);
        }
    }
}

// Precompute folded matrices A_g = W_g @ L_g[0:32,:], c_g = b_g @ L_g[0:32,:] + Lgb,
// and softmax(att). One block of 512 threads.
__global__ void k_prep(const float* __restrict__ Wz, const float* __restrict__ bz,
                       const float* __restrict__ Wr, const float* __restrict__ br,
                       const float* __restrict__ Wh, const float* __restrict__ bh,
                       const float* __restrict__ LzW, const float* __restrict__ Lzb,
                       const float* __restrict__ LrW, const float* __restrict__ Lrb,
                       const float* __restrict__ LhW, const float* __restrict__ Lhb,
                       const float* __restrict__ att) {
    int id = threadIdx.x;                       // 512 threads
    const float* W[3]  = {Wz, Wr, Wh};
    const float* L[3]  = {LzW, LrW, LhW};
    const float* bb[3] = {bz, br, bh};
    const float* Lb[3] = {Lzb, Lrb, Lhb};

    int f = id >> 5, j = id & 31;               // 16 x 32 = 512
    #pragma unroll
    for (int g = 0; g < 3; g++) {
        float s = 0.0f;
        #pragma unroll
        for (int k = 0; k < HID; k++)
            s = fmaf(W[g][f * HID + k], L[g][k * HID + j], s);
        g_A[(g * FIN + f) * HID + j] = s;
    }
    if (id < 3 * HID) {
        int g = id >> 5, jj = id & 31;
        float s = Lb[g][jj];
        #pragma unroll
        for (int k = 0; k < HID; k++)
            s = fmaf(bb[g][k], L[g][k * HID + jj], s);
        g_c[g * HID + jj] = s;
    }
    if (id == 0) {
        float m = att[0];
        for (int t = 1; t < TT; t++) m = fmaxf(m, att[t]);
        float sum = 0.0f;
        float ev[TT];
        for (int t = 0; t < TT; t++) { ev[t] = __expf(att[t] - m); sum += ev[t]; }
        float inv = __fdividef(1.0f, sum);
        for (int t = 0; t < TT; t++) g_probs[t] = ev[t] * inv;
    }
}

// ---- parallel 3-phase scan ----
__global__ void k_scan_a(int N) {
    __shared__ int ws[SB / 32];
    int tid = threadIdx.x;
    int i = blockIdx.x * SB + tid;
    int v = (i < N) ? g_cnt[i] : 0;
    #pragma unroll
    for (int o = 16; o; o >>= 1) v += __shfl_xor_sync(0xffffffffu, v, o);
    if ((tid & 31) == 0) ws[tid >> 5] = v;
    __syncthreads();
    if (tid < SB / 32) {
        int w = ws[tid];
        #pragma unroll
        for (int o = 8; o; o >>= 1) w += __shfl_xor_sync(0xffffu, w, o);
        if (tid == 0) g_part[blockIdx.x] = w;
    }
}

__global__ void k_scan_b(int NB, int N, int E) {
    __shared__ int ws[4];
    int tid = threadIdx.x, lane = tid & 31, wid = tid >> 5;
    int orig = (tid < NB) ? g_part[tid] : 0;
    int v = orig;
    #pragma unroll
    for (int o = 1; o < 32; o <<= 1) {
        int t = __shfl_up_sync(0xffffffffu, v, o);
        if (lane >= o) v += t;
    }
    if (lane == 31) ws[wid] = v;
    __syncthreads();
    if (wid == 0 && lane < 4) {
        int w = ws[lane];
        #pragma unroll
        for (int o = 1; o < 4; o <<= 1) {
            int t = __shfl_up_sync(0xfu, w, o);
            if (lane >= o) w += t;
        }
        ws[lane] = w;
    }
    __syncthreads();
    int incl = v + (wid > 0 ? ws[wid - 1] : 0);
    if (tid < NB) g_part[tid] = incl - orig;     // exclusive
    if (tid == 0) g_rowptr[N] = E;
}

__global__ void k_scan_c(int N) {
    __shared__ int ws[SB / 32];
    int tid = threadIdx.x, lane = tid & 31, wid = tid >> 5;
    int i = blockIdx.x * SB + tid;
    int c = (i < N) ? g_cnt[i] : 0;
    int v = c;
    #pragma unroll
    for (int o = 1; o < 32; o <<= 1) {
        int t = __shfl_up_sync(0xffffffffu, v, o);
        if (lane >= o) v += t;
    }
    if (lane == 31) ws[wid] = v;
    __syncthreads();
    if (wid == 0 && lane < SB / 32) {
        int w = ws[lane];
        #pragma unroll
        for (int o = 1; o < SB / 32; o <<= 1) {
            int t = __shfl_up_sync((1u << (SB / 32)) - 1u, w, o);
            if (lane >= o) w += t;
        }
        ws[lane] = w;
    }
    __syncthreads();
    int excl = v - c + (wid > 0 ? ws[wid - 1] : 0) + g_part[blockIdx.x];
    if (i < N) {
        g_rowptr[i] = excl;
        g_cur[i]    = excl;
        g_dis[i]    = rsqrtf((float)(c + 1));    // +1 self-loop
    }
}

// CSR fill with folded norm weight: payload {src, dis[s]*dis[d]}
__global__ void k_fill(const int* __restrict__ ei, int E) {
    int e = blockIdx.x * blockDim.x + threadIdx.x;
    if (e >= E) return;
    int s = ei[e];
    int d = ei[E + e];
    int p = atomicAdd(&g_cur[d], 1);
    g_sw[p] = make_int2(s, __float_as_int(g_dis[s] * g_dis[d]));
}

// Warp-per-node gather on fp16 features:
//   agg[n] = (1/deg)*xh[n] + sum_edges w*xh[s]      (fp32 accumulation)
// Lane l (<24) owns values 8l..8l+7 of the 192 (one float4 of halves = 8 values).
__global__ void __launch_bounds__(256)
k_gather(int N) {
    __shared__ int2 stage[8][32];
    int gw   = (blockIdx.x * blockDim.x + threadIdx.x) >> 5;
    int wloc = threadIdx.x >> 5;
    int lane = threadIdx.x & 31;
    if (gw >= N) return;
    int n = gw;

    int beg = g_rowptr[n];
    int end = g_rowptr[n + 1];
    float dd = g_dis[n];
    bool act = lane < 24;

    float acc[8];
    if (act) {
        float inv = dd * dd;                       // 1/deg (self-loop term)
        F4H2 v; v.f4 = ((const float4*)(g_xh + (size_t)n * FT))[lane];
        #pragma unroll
        for (int q = 0; q < 4; q++) {
            float2 f = __half22float2(v.h2[q]);
            acc[2 * q]     = inv * f.x;
            acc[2 * q + 1] = inv * f.y;
        }
    }

    for (int i = beg; i < end; i += 32) {
        int j = i + lane;
        if (j < end) stage[wloc][lane] = g_sw[j];
        __syncwarp();
        int m = min(32, end - i);
        #pragma unroll 2
        for (int u = 0; u < m; u++) {
            int2 sw = stage[wloc][u];
            if (act) {
                float ww = __int_as_float(sw.y);
                F4H2 v; v.f4 = ((const float4*)(g_xh + (size_t)sw.x * FT))[lane];
                #pragma unroll
                for (int q = 0; q < 4; q++) {
                    float2 f = __half22float2(v.h2[q]);
                    acc[2 * q]     = fmaf(ww, f.x, acc[2 * q]);
                    acc[2 * q + 1] = fmaf(ww, f.y, acc[2 * q + 1]);
                }
            }
        }
        __syncwarp();
    }

    if (act) {
        float4* ap = (float4*)(g_agg + (size_t)n * FT);
        ap[2 * lane]     = make_float4(acc[0], acc[1], acc[2], acc[3]);
        ap[2 * lane + 1] = make_float4(acc[4], acc[5], acc[6], acc[7]);
    }
}

// Per-node GRU over T=12 steps, packed f32x2 math; weights in shared.
// agg is t-major: a[16] for (n,t) is 64B contiguous.
__global__ void __launch_bounds__(128, 2)
k_gru(const float* __restrict__ LzW, const float* __restrict__ LrW,
      const float* __restrict__ LhW, int N) {
    __shared__ float4 sA[3][FIN][HID / 4];   // folded A matrices
    __shared__ float4 sB[3][HID][HID / 4];   // bottom halves of L matrices
    __shared__ float4 sc[3][HID / 4];        // folded biases
    __shared__ float  sp[TT];
    __shared__ float  bsum[HID];

    int tid = threadIdx.x;
    {
        float* pA = (float*)sA;
        for (int i = tid; i < 3 * FIN * HID; i += 128) pA[i] = g_A[i];
        float* pB = (float*)sB;
        for (int i = tid; i < HID * HID; i += 128) {
            pB[i]                 = LzW[HID * HID + i];
            pB[HID * HID + i]     = LrW[HID * HID + i];
            pB[2 * HID * HID + i] = LhW[HID * HID + i];
        }
        float* pc = (float*)sc;
        if (tid < 3 * HID) pc[tid] = g_c[tid];
        if (tid < TT) sp[tid] = g_probs[tid];
        if (tid < HID) bsum[tid] = 0.0f;
    }
    __syncthreads();

    int n = blockIdx.x * 128 + tid;
    if (n < N) {
        float H[HID], acc[HID];
        #pragma unroll
        for (int j = 0; j < HID; j++) { H[j] = 0.0f; acc[j] = 0.0f; }
        const float4* ap4 = (const float4*)(g_agg + (size_t)n * FT);

        #pragma unroll 1
        for (int t = 0; t < TT; t++) {
            float a[FIN];
            {
                float4 a0 = __ldg(&ap4[4 * t + 0]);
                float4 a1 = __ldg(&ap4[4 * t + 1]);
                float4 a2 = __ldg(&ap4[4 * t + 2]);
                float4 a3 = __ldg(&ap4[4 * t + 3]);
                a[0] = a0.x;  a[1] = a0.y;  a[2] = a0.z;  a[3] = a0.w;
                a[4] = a1.x;  a[5] = a1.y;  a[6] = a1.z;  a[7] = a1.w;
                a[8] = a2.x;  a[9] = a2.y;  a[10] = a2.z; a[11] = a2.w;
                a[12] = a3.x; a[13] = a3.y; a[14] = a3.z; a[15] = a3.w;
            }
            float p = sp[t];

            // hoisted packed broadcasts of a
            u64 apk[FIN];
            #pragma unroll
            for (int f = 0; f < FIN; f++) apk[f] = pk2(a[f], a[f]);

            // ---- z, r pre-activations (packed pairs) ----
            u64 z[HID / 2], r[HID / 2];
            #pragma unroll
            for (int j4 = 0; j4 < HID / 4; j4++) {
                F4U2 cz; cz.f4 = sc[0][j4];
                F4U2 cr; cr.f4 = sc[1][j4];
                z[2 * j4] = cz.u[0]; z[2 * j4 + 1] = cz.u[1];
                r[2 * j4] = cr.u[0]; r[2 * j4 + 1] = cr.u[1];
            }
            #pragma unroll 4
            for (int f = 0; f < FIN; f++) {
                u64 av = apk[f];
                #pragma unroll
                for (int j4 = 0; j4 < HID / 4; j4++) {
                    F4U2 wz; wz.f4 = sA[0][f][j4];
                    F4U2 wr; wr.f4 = sA[1][f][j4];
                    z[2 * j4]     = fma2(av, wz.u[0], z[2 * j4]);
                    z[2 * j4 + 1] = fma2(av, wz.u[1], z[2 * j4 + 1]);
                    r[2 * j4]     = fma2(av, wr.u[0], r[2 * j4]);
                    r[2 * j4 + 1] = fma2(av, wr.u[1], r[2 * j4 + 1]);
                }
            }
            #pragma unroll 4
            for (int k = 0; k < HID; k++) {
                u64 hk = pk2(H[k], H[k]);
                #pragma unroll
                for (int j4 = 0; j4 < HID / 4; j4++) {
                    F4U2 wz; wz.f4 = sB[0][k][j4];
                    F4U2 wr; wr.f4 = sB[1][k][j4];
                    z[2 * j4]     = fma2(hk, wz.u[0], z[2 * j4]);
                    z[2 * j4 + 1] = fma2(hk, wz.u[1], z[2 * j4 + 1]);
                    r[2 * j4]     = fma2(hk, wr.u[0], r[2 * j4]);
                    r[2 * j4 + 1] = fma2(hk, wr.u[1], r[2 * j4 + 1]);
                }
            }
            float Z[HID], R[HID];
            #pragma unroll
            for (int j2 = 0; j2 < HID / 2; j2++) {
                float x0, x1;
                up2(z[j2], x0, x1);
                Z[2 * j2] = sigf(x0); Z[2 * j2 + 1] = sigf(x1);
                up2(r[j2], x0, x1);
                R[2 * j2]     = sigf(x0) * H[2 * j2];
                R[2 * j2 + 1] = sigf(x1) * H[2 * j2 + 1];
            }

            // ---- candidate h (packed pairs) ----
            u64 h[HID / 2];
            #pragma unroll
            for (int j4 = 0; j4 < HID / 4; j4++) {
                F4U2 ch; ch.f4 = sc[2][j4];
                h[2 * j4] = ch.u[0]; h[2 * j4 + 1] = ch.u[1];
            }
            #pragma unroll 4
            for (int f = 0; f < FIN; f++) {
                u64 av = apk[f];
                #pragma unroll
                for (int j4 = 0; j4 < HID / 4; j4++) {
                    F4U2 wh; wh.f4 = sA[2][f][j4];
                    h[2 * j4]     = fma2(av, wh.u[0], h[2 * j4]);
                    h[2 * j4 + 1] = fma2(av, wh.u[1], h[2 * j4 + 1]);
                }
            }
            #pragma unroll 4
            for (int k = 0; k < HID; k++) {
                u64 rk = pk2(R[k], R[k]);
                #pragma unroll
                for (int j4 = 0; j4 < HID / 4; j4++) {
                    F4U2 wh; wh.f4 = sB[2][k][j4];
                    h[2 * j4]     = fma2(rk, wh.u[0], h[2 * j4]);
                    h[2 * j4 + 1] = fma2(rk, wh.u[1], h[2 * j4 + 1]);
                }
            }
            #pragma unroll
            for (int j2 = 0; j2 < HID / 2; j2++) {
                float h0, h1;
                up2(h[j2], h0, h1);
                int j = 2 * j2;
                {
                    float ht = tanhfast(h0); float zt = Z[j];
                    H[j] = zt * H[j] + (1.0f - zt) * ht;
                    acc[j] = fmaf(p, H[j], acc[j]);
                }
                {
                    float ht = tanhfast(h1); float zt = Z[j + 1];
                    H[j + 1] = zt * H[j + 1] + (1.0f - zt) * ht;
                    acc[j + 1] = fmaf(p, H[j + 1], acc[j + 1]);
                }
            }
        }
        #pragma unroll
        for (int j = 0; j < HID; j++) {
            float v = acc[j] > 0.0f ? acc[j] : 0.0f;
            atomicAdd(&bsum[j], v);
        }
    }
    __syncthreads();
    if (tid < HID) atomicAdd(&g_hsum[tid], bsum[tid]);
}

__global__ void k_final(const float* __restrict__ linW, const float* __restrict__ linb,
                        float* out, int N) {
    int j = threadIdx.x;   // 32 threads
    float invN = 1.0f / (float)N;
    float v = g_hsum[j] * invN * linW[j];
    #pragma unroll
    for (int o = 16; o; o >>= 1) v += __shfl_xor_sync(0xffffffffu, v, o);
    if (j == 0) {
        float r = v + linb[0];
        out[0] = r > 0.0f ? r : 0.0f;
    }
}

// ---------------- launcher ----------------
extern "C" void kernel_launch(void* const* d_in, const int* in_sizes, int n_in,
                              void* d_out, int out_size) {
    const float* x    = (const float*)d_in[0];
    const int*   ei   = (const int*)  d_in[1];
    const float* att  = (const float*)d_in[2];
    const float* Wz   = (const float*)d_in[3];
    const float* bz   = (const float*)d_in[4];
    const float* Wr   = (const float*)d_in[5];
    const float* br   = (const float*)d_in[6];
    const float* Wh   = (const float*)d_in[7];
    const float* bh   = (const float*)d_in[8];
    const float* LzW  = (const float*)d_in[9];
    const float* Lzb  = (const float*)d_in[10];
    const float* LrW  = (const float*)d_in[11];
    const float* Lrb  = (const float*)d_in[12];
    const float* LhW  = (const float*)d_in[13];
    const float* Lhb  = (const float*)d_in[14];
    const float* linW = (const float*)d_in[15];
    const float* linb = (const float*)d_in[16];

    int N = in_sizes[0] / FT;
    int E = in_sizes[1] / 2;
    int NB = (N + SB - 1) / SB;

    k_zero<<<(N + 255) / 256, 256>>>(N);
    k_cnt<<<(E + 255) / 256, 256>>>(ei, E);
    k_half<<<(N + 3) / 4, 256>>>(x, N);
    k_prep<<<1, 512>>>(Wz, bz, Wr, br, Wh, bh, LzW, Lzb, LrW, Lrb, LhW, Lhb, att);
    k_scan_a<<<NB, SB>>>(N);
    k_scan_b<<<1, 128>>>(NB, N, E);
    k_scan_c<<<NB, SB>>>(N);
    k_fill<<<(E + 255) / 256, 256>>>(ei, E);
    k_gather<<<(N * 32 + 255) / 256, 256>>>(N);
    k_gru<<<(N + 127) / 128, 128>>>(LzW, LrW, LhW, N);
    k_final<<<1, 32>>>(linW, linb, (float*)d_out, N);
}